// round 3
// baseline (speedup 1.0000x reference)
#include <cuda_runtime.h>
#include <math.h>

#define HID   256
#define B_    16
#define T_    1024
#define S_    256
#define MMAX  5151
#define CB    9        // chunk-blocks per batch in the scan
#define SCAN_TPB 256
#define PPT   3        // points per thread in the scan

// -------- scratch (static device globals; no runtime allocation) ----------
__device__ float g_density[MMAX + 32];
__device__ float g_dsum;
__device__ float g_ctxw[B_ * HID];                 // ctx @ Wc + bm
__device__ float g_init[B_ * MMAX + 32];           // initial states
__device__ float g_partial[B_ * CB * 8 * T_];      // per-warp partial sums

__device__ __forceinline__ float sigmoidf_(float x) { return 1.0f / (1.0f + expf(-x)); }
__device__ __forceinline__ float tanh_fast(float x) {
    float y; asm("tanh.approx.f32 %0, %1;" : "=f"(y) : "f"(x)); return y;
}

// ---------------- K1: density MLP (batch-independent) ---------------------
// 16 mesh rows per block, 256 threads = one output column each.
__global__ void k_density(const float* __restrict__ mesh,
                          const float* __restrict__ Win, const float* __restrict__ bin,
                          const float* __restrict__ Wr,  const float* __restrict__ br,
                          const float* __restrict__ Wout,const float* __restrict__ bout,
                          int M)
{
    __shared__ float hA[16][HID];
    __shared__ float sB[16][HID];
    const int c  = threadIdx.x;
    const int r0 = blockIdx.x * 16;

    float w0 = Win[c], w1 = Win[HID + c], bi = bin[c];
#pragma unroll
    for (int r = 0; r < 16; ++r) {
        int row = r0 + r;
        float be = 0.f, al = 0.f;
        if (row < M) { be = mesh[row * 2]; al = mesh[row * 2 + 1]; }
        float v = fmaf(be, w0, fmaf(al, w1, bi));
        hA[r][c] = fmaxf(v, 0.f);
    }
    __syncthreads();

    for (int l = 0; l < 3; ++l) {
        float acc[16];
        float bb = br[l * HID + c];
#pragma unroll
        for (int r = 0; r < 16; ++r) acc[r] = bb;
        const float* W = Wr + l * HID * HID + c;
#pragma unroll 4
        for (int k = 0; k < HID; ++k) {
            float w = W[k * HID];
#pragma unroll
            for (int r = 0; r < 16; ++r) acc[r] = fmaf(hA[r][k], w, acc[r]);
        }
        __syncthreads();
#pragma unroll
        for (int r = 0; r < 16; ++r) hA[r][c] += fmaxf(acc[r], 0.f);
        __syncthreads();
    }

    float wo = Wout[c];
#pragma unroll
    for (int r = 0; r < 16; ++r) sB[r][c] = hA[r][c] * wo;
    __syncthreads();

    int warp = c >> 5, lane = c & 31;
    float bo = bout[0];
    for (int rr = warp; rr < 16; rr += 8) {
        float v = 0.f;
#pragma unroll
        for (int i = 0; i < 8; ++i) v += sB[rr][lane + i * 32];
#pragma unroll
        for (int o = 16; o > 0; o >>= 1) v += __shfl_xor_sync(0xffffffffu, v, o);
        if (lane == 0) {
            int row = r0 + rr;
            if (row < M) g_density[row] = sigmoidf_(v + bo);
        }
    }
}

// ---------------- K1b: dsum -----------------------------------------------
__global__ void k_dsum(int M)
{
    __shared__ float red[256];
    float s = 0.f;
    for (int i = threadIdx.x; i < M; i += 256) s += g_density[i];
    red[threadIdx.x] = s;
    __syncthreads();
    for (int o = 128; o > 0; o >>= 1) {
        if (threadIdx.x < o) red[threadIdx.x] += red[threadIdx.x + o];
        __syncthreads();
    }
    if (threadIdx.x == 0) g_dsum = red[0];
}

// ---------------- K2: encoder ctx -> ctx@Wc + bm --------------------------
__global__ void k_ctx(const float* __restrict__ enc_in, const float* __restrict__ maskp,
                      const float* __restrict__ Ws, const float* __restrict__ bs,
                      const float* __restrict__ Wc, const float* __restrict__ bm)
{
    __shared__ float ctx_s[HID];
    int b = blockIdx.x, c = threadIdx.x;
    float w0 = Ws[c], w1 = Ws[HID + c], bb = bs[c];
    float acc = 0.f, msum = 0.f;
    for (int s = 0; s < S_; ++s) {
        float mk = maskp[b * S_ + s];
        float e0 = enc_in[(b * S_ + s) * 2];
        float e1 = enc_in[(b * S_ + s) * 2 + 1];
        float v  = fmaxf(fmaf(e0, w0, fmaf(e1, w1, bb)), 0.f);
        acc  = fmaf(v, mk, acc);
        msum += mk;
    }
    ctx_s[c] = acc / fmaxf(msum, 1.0f);
    __syncthreads();
    float cw = bm[c];
    for (int k = 0; k < HID; ++k) cw = fmaf(ctx_s[k], Wc[k * HID + c], cw);
    g_ctxw[b * HID + c] = cw;
}

// ---------------- K3: initial states + out density/mesh replication -------
// one warp per (b, j)
__global__ void k_init(const float* __restrict__ mesh,
                       const float* __restrict__ Wm, const float* __restrict__ Wo,
                       const float* __restrict__ bo,
                       float* __restrict__ out_init, float* __restrict__ out_dens,
                       float* __restrict__ out_mesh, int M)
{
    __shared__ float sW[HID * 3];
    __shared__ float sWo[HID];
    int tid = threadIdx.x;
    for (int i = tid; i < HID * 3; i += 256) sW[i]  = Wm[i];
    for (int i = tid; i < HID;     i += 256) sWo[i] = Wo[i];
    __syncthreads();

    int wg = blockIdx.x * 8 + (tid >> 5);
    int lane = tid & 31;
    if (wg >= B_ * M) return;
    int b = wg / M, j = wg - b * M;

    float be = mesh[j * 2], al = mesh[j * 2 + 1], de = g_density[j];
    const float* cw = g_ctxw + b * HID;
    float acc = 0.f;
#pragma unroll
    for (int i = 0; i < 8; ++i) {
        int c = i * 32 + lane;
        float z = fmaf(be, sW[c], fmaf(al, sW[HID + c], fmaf(de, sW[2 * HID + c], cw[c])));
        z = fmaxf(z, 0.f);
        acc = fmaf(z, sWo[c], acc);
    }
#pragma unroll
    for (int o = 16; o > 0; o >>= 1) acc += __shfl_xor_sync(0xffffffffu, acc, o);
    if (lane == 0) {
        float is = tanhf(acc + bo[0]);
        g_init[wg]          = is;
        out_init[wg]        = is;
        out_dens[wg]        = de;
        out_mesh[wg * 2]    = be;
        out_mesh[wg * 2 + 1]= al;
    }
}

// ---------------- K4: relay scan (the hot kernel) -------------------------
// grid = B*CB blocks, 256 thr, up to 3 points/thread, per-warp partial sums.
__global__ void __launch_bounds__(SCAN_TPB)
k_scan(const float* __restrict__ mesh, const float* __restrict__ dec, int M)
{
    __shared__ float hs[T_];
    int tid = threadIdx.x;
    int b   = blockIdx.x / CB;
    int cb  = blockIdx.x % CB;
    int chunk = (M + CB - 1) / CB;
    int j0  = cb * chunk;
    int n   = min(chunk, M - j0);

    for (int t = tid; t < T_; t += SCAN_TPB) hs[t] = dec[b * T_ + t] * 500.f;

    float a5[PPT], b5[PPT], de[PPT], s[PPT];
#pragma unroll
    for (int i = 0; i < PPT; ++i) {
        int off = i * SCAN_TPB + tid;
        if (off < n) {
            int j = j0 + off;
            b5[i] = mesh[j * 2]     * 500.f;   // beta * (1/(2*TEMP))
            a5[i] = mesh[j * 2 + 1] * 500.f;   // alpha * (1/(2*TEMP))
            de[i] = g_density[j];
            s[i]  = g_init[b * M + j];
        } else {
            a5[i] = 1e9f; b5[i] = -1e9f; de[i] = 0.f; s[i] = 0.f;  // w_up=w_dn=0
        }
    }
    __syncthreads();

    int warp = tid >> 5, lane = tid & 31;
    float* outp = g_partial + (((b * CB + cb) * 8 + warp) * T_);

    for (int t = 0; t < T_; ++t) {
        float ht  = hs[t];
        float acc = 0.f;
#pragma unroll
        for (int i = 0; i < PPT; ++i) {
            // sigmoid(z/TEMP) = 0.5*tanh(z*500) + 0.5  (one MUFU.TANH each)
            float wu = fmaf(0.5f, tanh_fast(ht - a5[i]), 0.5f);
            float wd = fmaf(0.5f, tanh_fast(b5[i] - ht), 0.5f);
            float sv = s[i];
            float s1 = fmaf(wu,  1.0f - sv, sv);
            float s2 = fmaf(wd, -1.0f - s1, s1);
            s[i] = s2;
            acc = fmaf(de[i], s2, acc);
        }
#pragma unroll
        for (int o = 16; o > 0; o >>= 1) acc += __shfl_xor_sync(0xffffffffu, acc, o);
        if (lane == 0) outp[t] = acc;
    }
}

// ---------------- K5: reduce partials, scales, b_out ----------------------
__global__ void k_final(const float* __restrict__ dec,
                        const float* __restrict__ hr, const float* __restrict__ mr,
                        const float* __restrict__ offr,
                        float* __restrict__ out_b, float* __restrict__ out_m)
{
    int idx = blockIdx.x * 256 + threadIdx.x;      // 0 .. B*T-1
    int b = idx >> 10, t = idx & 1023;
    float sum = 0.f;
    const float* pp = g_partial + (b * CB * 8) * T_ + t;
#pragma unroll
    for (int p = 0; p < CB * 8; ++p) sum += pp[p * T_];
    float m = sum / g_dsum;

    float hsc = 10.f * sigmoidf_(hr[0]);                 // [0,10]
    float msc = 10.f * sigmoidf_(mr[0]);                 // [0,10]
    float mof = fmaf(20.f, sigmoidf_(offr[0]), -10.f);   // [-10,10]

    float hv = dec[idx];
    out_b[idx] = fmaf(hsc, hv, fmaf(msc, m, mof));
    out_m[idx] = m;
    (void)b; (void)t;
}

// ---------------- host launcher -------------------------------------------
extern "C" void kernel_launch(void* const* d_in, const int* in_sizes, int n_in,
                              void* d_out, int out_size)
{
    const float* enc_in = (const float*)d_in[0];
    const float* dec    = (const float*)d_in[1];
    const float* maskp  = (const float*)d_in[2];
    const float* mesh   = (const float*)d_in[3];
    const float* dWin   = (const float*)d_in[4];
    const float* dbin   = (const float*)d_in[5];
    const float* dWr    = (const float*)d_in[6];
    const float* dbr    = (const float*)d_in[7];
    const float* dWout  = (const float*)d_in[8];
    const float* dbout  = (const float*)d_in[9];
    const float* eWs    = (const float*)d_in[10];
    const float* ebs    = (const float*)d_in[11];
    const float* eWm    = (const float*)d_in[12];
    const float* eWc    = (const float*)d_in[13];
    const float* ebm    = (const float*)d_in[14];
    const float* eWo    = (const float*)d_in[15];
    const float* ebo    = (const float*)d_in[16];
    const float* hr     = (const float*)d_in[17];
    const float* mr     = (const float*)d_in[18];
    const float* offr   = (const float*)d_in[19];

    const int M = in_sizes[3] / 2;   // 5151

    // output layout: concat of (b_out, density, m, initial_states, mesh)
    float* out      = (float*)d_out;
    float* out_b    = out;
    float* out_dens = out_b    + B_ * T_;
    float* out_m    = out_dens + B_ * M;
    float* out_init = out_m    + B_ * T_;
    float* out_mesh = out_init + B_ * M;

    k_density<<<(M + 15) / 16, 256>>>(mesh, dWin, dbin, dWr, dbr, dWout, dbout, M);
    k_dsum<<<1, 256>>>(M);
    k_ctx<<<B_, 256>>>(enc_in, maskp, eWs, ebs, eWc, ebm);
    k_init<<<(B_ * M + 7) / 8, 256>>>(mesh, eWm, eWo, ebo, out_init, out_dens, out_mesh, M);
    k_scan<<<B_ * CB, SCAN_TPB>>>(mesh, dec, M);
    k_final<<<(B_ * T_) / 256, 256>>>(dec, hr, mr, offr, out_b, out_m);

    (void)n_in; (void)out_size;
}

// round 4
// speedup vs baseline: 1.2063x; 1.2063x over previous
#include <cuda_runtime.h>
#include <math.h>

#define HID   256
#define B_    16
#define T_    1024
#define S_    256
#define MMAX  5151
#define NSLOT 80          // max tile slots per batch in g_partial

// -------- scratch (static device globals; no runtime allocation) ----------
__device__ float g_density[MMAX + 32];
__device__ float g_dsum;
__device__ float g_ctxw[B_ * HID];                         // ctx @ Wc + bm
__device__ float g_init[B_ * MMAX + 32];                   // initial states
__device__ float g_partial[(size_t)B_ * NSLOT * T_ * 8];   // per-warp 8-wide partials

struct Tiles {
    int nt;          // number of tiles
    int n;           // grid points per axis (101)
    short tb[120];
    short ta[120];
};

__device__ __forceinline__ float sigmoidf_(float x) { return 1.0f / (1.0f + expf(-x)); }
__device__ __forceinline__ float tanh_fast(float x) {
    float y; asm("tanh.approx.f32 %0, %1;" : "=f"(y) : "f"(x)); return y;
}
__device__ __forceinline__ float warp_min(float v) {
#pragma unroll
    for (int o = 16; o > 0; o >>= 1) v = fminf(v, __shfl_xor_sync(0xffffffffu, v, o));
    return v;
}
__device__ __forceinline__ float warp_max(float v) {
#pragma unroll
    for (int o = 16; o > 0; o >>= 1) v = fmaxf(v, __shfl_xor_sync(0xffffffffu, v, o));
    return v;
}

// ---------------- K1: density MLP (batch-independent) ---------------------
// 16 mesh rows per block, 128 threads: each thread computes 16 rows x 2 cols.
__global__ void __launch_bounds__(128)
k_density(const float* __restrict__ mesh,
          const float* __restrict__ Win, const float* __restrict__ bin,
          const float* __restrict__ Wr,  const float* __restrict__ br,
          const float* __restrict__ Wout,const float* __restrict__ bout,
          int M)
{
    __shared__ float hA[16][HID];       // activations (16 KB)
    __shared__ float sB[16][128];       // output reduction (8 KB)
    const int tid = threadIdx.x;
    const int c0  = tid;                // columns c0 and c0+128
    const int c1  = tid + 128;
    const int r0  = blockIdx.x * 16;

    // ---- input layer ----
    {
        float wa0 = Win[c0], wb0 = Win[HID + c0], bi0 = bin[c0];
        float wa1 = Win[c1], wb1 = Win[HID + c1], bi1 = bin[c1];
#pragma unroll
        for (int r = 0; r < 16; ++r) {
            int row = r0 + r;
            float be = 0.f, al = 0.f;
            if (row < M) { be = mesh[row * 2]; al = mesh[row * 2 + 1]; }
            hA[r][c0] = fmaxf(fmaf(be, wa0, fmaf(al, wb0, bi0)), 0.f);
            hA[r][c1] = fmaxf(fmaf(be, wa1, fmaf(al, wb1, bi1)), 0.f);
        }
    }
    __syncthreads();

    // ---- residual layers ----
    for (int l = 0; l < 3; ++l) {
        float acc0[16], acc1[16];
        float bb0 = br[l * HID + c0], bb1 = br[l * HID + c1];
#pragma unroll
        for (int r = 0; r < 16; ++r) { acc0[r] = bb0; acc1[r] = bb1; }
        const float* W = Wr + l * HID * HID;
#pragma unroll 2
        for (int k = 0; k < HID; k += 4) {
            float w0[4], w1[4];
#pragma unroll
            for (int kk = 0; kk < 4; ++kk) {
                w0[kk] = W[(k + kk) * HID + c0];
                w1[kk] = W[(k + kk) * HID + c1];
            }
#pragma unroll
            for (int r = 0; r < 16; ++r) {
                float4 a = *(const float4*)&hA[r][k];
                acc0[r] = fmaf(a.x, w0[0], fmaf(a.y, w0[1], fmaf(a.z, w0[2], fmaf(a.w, w0[3], acc0[r]))));
                acc1[r] = fmaf(a.x, w1[0], fmaf(a.y, w1[1], fmaf(a.z, w1[2], fmaf(a.w, w1[3], acc1[r]))));
            }
        }
        __syncthreads();
#pragma unroll
        for (int r = 0; r < 16; ++r) {
            hA[r][c0] += fmaxf(acc0[r], 0.f);
            hA[r][c1] += fmaxf(acc1[r], 0.f);
        }
        __syncthreads();
    }

    // ---- output layer + sigmoid ----
    {
        float wo0 = Wout[c0], wo1 = Wout[c1];
#pragma unroll
        for (int r = 0; r < 16; ++r)
            sB[r][tid] = fmaf(hA[r][c0], wo0, hA[r][c1] * wo1);
    }
    __syncthreads();

    int warp = tid >> 5, lane = tid & 31;
    float bo = bout[0];
    for (int rr = warp; rr < 16; rr += 4) {
        float v = (sB[rr][lane] + sB[rr][lane + 32]) + (sB[rr][lane + 64] + sB[rr][lane + 96]);
#pragma unroll
        for (int o = 16; o > 0; o >>= 1) v += __shfl_xor_sync(0xffffffffu, v, o);
        if (lane == 0) {
            int row = r0 + rr;
            if (row < M) g_density[row] = sigmoidf_(v + bo);
        }
    }
}

// ---------------- K1b: dsum -----------------------------------------------
__global__ void k_dsum(int M)
{
    __shared__ float red[256];
    float s = 0.f;
    for (int i = threadIdx.x; i < M; i += 256) s += g_density[i];
    red[threadIdx.x] = s;
    __syncthreads();
    for (int o = 128; o > 0; o >>= 1) {
        if (threadIdx.x < o) red[threadIdx.x] += red[threadIdx.x + o];
        __syncthreads();
    }
    if (threadIdx.x == 0) g_dsum = red[0];
}

// ---------------- K2: encoder ctx -> ctx@Wc + bm --------------------------
__global__ void k_ctx(const float* __restrict__ enc_in, const float* __restrict__ maskp,
                      const float* __restrict__ Ws, const float* __restrict__ bs,
                      const float* __restrict__ Wc, const float* __restrict__ bm)
{
    __shared__ float ctx_s[HID];
    int b = blockIdx.x, c = threadIdx.x;
    float w0 = Ws[c], w1 = Ws[HID + c], bb = bs[c];
    float acc = 0.f, msum = 0.f;
    for (int s = 0; s < S_; ++s) {
        float mk = maskp[b * S_ + s];
        float e0 = enc_in[(b * S_ + s) * 2];
        float e1 = enc_in[(b * S_ + s) * 2 + 1];
        float v  = fmaxf(fmaf(e0, w0, fmaf(e1, w1, bb)), 0.f);
        acc  = fmaf(v, mk, acc);
        msum += mk;
    }
    ctx_s[c] = acc / fmaxf(msum, 1.0f);
    __syncthreads();
    float cw = bm[c];
    for (int k = 0; k < HID; ++k) cw = fmaf(ctx_s[k], Wc[k * HID + c], cw);
    g_ctxw[b * HID + c] = cw;
}

// ---------------- K3: initial states (thread per (b,j)) -------------------
__global__ void __launch_bounds__(128)
k_init(const float* __restrict__ mesh,
       const float* __restrict__ Wm, const float* __restrict__ Wo,
       const float* __restrict__ bo,
       float* __restrict__ out_init, float* __restrict__ out_dens,
       float* __restrict__ out_mesh, int M)
{
    __shared__ float4 sw4[HID];
    __shared__ float  scw[HID];
    int tid = threadIdx.x;
    int b   = blockIdx.y;
    for (int i = tid; i < HID; i += 128) {
        sw4[i] = make_float4(Wm[i], Wm[HID + i], Wm[2 * HID + i], Wo[i]);
        scw[i] = g_ctxw[b * HID + i];
    }
    __syncthreads();

    int j = blockIdx.x * 128 + tid;
    if (j >= M) return;

    float be = mesh[j * 2], al = mesh[j * 2 + 1], de = g_density[j];
    float a0 = 0.f, a1 = 0.f, a2 = 0.f, a3 = 0.f;
#pragma unroll 4
    for (int c = 0; c < HID; c += 4) {
        float4 w;
        float z;
        w = sw4[c + 0]; z = fmaxf(fmaf(be, w.x, fmaf(al, w.y, fmaf(de, w.z, scw[c + 0]))), 0.f); a0 = fmaf(z, w.w, a0);
        w = sw4[c + 1]; z = fmaxf(fmaf(be, w.x, fmaf(al, w.y, fmaf(de, w.z, scw[c + 1]))), 0.f); a1 = fmaf(z, w.w, a1);
        w = sw4[c + 2]; z = fmaxf(fmaf(be, w.x, fmaf(al, w.y, fmaf(de, w.z, scw[c + 2]))), 0.f); a2 = fmaf(z, w.w, a2);
        w = sw4[c + 3]; z = fmaxf(fmaf(be, w.x, fmaf(al, w.y, fmaf(de, w.z, scw[c + 3]))), 0.f); a3 = fmaf(z, w.w, a3);
    }
    float is = tanhf((a0 + a1) + (a2 + a3) + bo[0]);
    int wg = b * M + j;
    g_init[wg]           = is;
    out_init[wg]         = is;
    out_dens[wg]         = de;
    out_mesh[wg * 2]     = be;
    out_mesh[wg * 2 + 1] = al;
}

// ---------------- K4: relay scan (hot kernel, tile-per-warp) ---------------
// grid = (groups, B). Each warp owns one 8x12 (beta,alpha) tile (<=96 points,
// 3 per lane). Per step: warp-uniform saturation test; clean path = cmp/sel
// (no MUFU), dirty path = tanh. 2-shfl reduction -> 8 contiguous partials.
__global__ void __launch_bounds__(256)
k_scan(const float* __restrict__ mesh, const float* __restrict__ dec, int M, Tiles tl)
{
    __shared__ float hs[T_];
    int tid = threadIdx.x, lane = tid & 31, warp = tid >> 5;
    int b = blockIdx.y, tg = blockIdx.x;

    for (int t = tid; t < T_; t += 256) hs[t] = dec[b * T_ + t] * 500.f;
    __syncthreads();

    int tile = tg * 8 + warp;
    if (tile >= tl.nt) return;

    const int n  = tl.n;
    const int tb = tl.tb[tile], ta = tl.ta[tile];

    float a5[3], b5[3], de[3], s[3];
    float amin = 1e30f, amax = -1e30f, bmin = 1e30f, bmax = -1e30f;
#pragma unroll
    for (int i = 0; i < 3; ++i) {
        int cell = lane + 32 * i;
        int rib = cell / 12, ria = cell - rib * 12;
        int ib = tb * 8 + rib, ia = ta * 12 + ria;
        if (ib < n && ia < n && ia >= ib) {
            int j = ib * n - (ib * (ib - 1)) / 2 + (ia - ib);
            float be = mesh[2 * j] * 500.f;
            float al = mesh[2 * j + 1] * 500.f;
            a5[i] = al; b5[i] = be;
            de[i] = g_density[j];
            s[i]  = g_init[b * M + j];
            amin = fminf(amin, al); amax = fmaxf(amax, al);
            bmin = fminf(bmin, be); bmax = fmaxf(bmax, be);
        } else {
            a5[i] = 4000.f; b5[i] = -4000.f; de[i] = 0.f; s[i] = 0.f;
        }
    }
    // conservative saturation bounds (tanh(+-10.5) ~ +-1 to <1e-7)
    amin = warp_min(amin) - 10.5f;  amax = warp_max(amax) + 10.5f;
    bmin = warp_min(bmin) - 10.5f;  bmax = warp_max(bmax) + 10.5f;

    float* outp = g_partial + ((size_t)(b * NSLOT + tile)) * (T_ * 8);

    for (int t = 0; t < T_; ++t) {
        float ht5 = hs[t];
        float acc = 0.f;
        bool dirty = (ht5 > amin && ht5 < amax) || (ht5 > bmin && ht5 < bmax);
        if (dirty) {
#pragma unroll
            for (int i = 0; i < 3; ++i) {
                float u  = tanh_fast(ht5 - a5[i]);
                float d  = tanh_fast(b5[i] - ht5);
                float wu = fmaf(0.5f, u, 0.5f);
                float wd = fmaf(0.5f, d, 0.5f);
                float sv = s[i];
                float s1 = fmaf(wu,  1.0f - sv, sv);
                float s2 = fmaf(wd, -1.0f - s1, s1);
                s[i] = s2;
                acc = fmaf(de[i], s2, acc);
            }
        } else {
#pragma unroll
            for (int i = 0; i < 3; ++i) {
                float sv = s[i];
                sv = (ht5 > a5[i]) ?  1.0f : sv;
                sv = (ht5 < b5[i]) ? -1.0f : sv;
                s[i] = sv;
                acc = fmaf(de[i], sv, acc);
            }
        }
        acc += __shfl_xor_sync(0xffffffffu, acc, 16);
        acc += __shfl_xor_sync(0xffffffffu, acc, 8);
        if (lane < 8) outp[t * 8 + lane] = acc;
    }
}

// ---------------- K5: reduce partials, scales, b_out ----------------------
__global__ void k_final(const float* __restrict__ dec,
                        const float* __restrict__ hr, const float* __restrict__ mr,
                        const float* __restrict__ offr,
                        float* __restrict__ out_b, float* __restrict__ out_m,
                        int nt)
{
    int idx = blockIdx.x * 256 + threadIdx.x;     // 0 .. B*T-1
    int b = idx >> 10, t = idx & 1023;
    const float* base = g_partial + (size_t)b * NSLOT * (T_ * 8) + (size_t)t * 8;
    float s0 = 0.f, s1 = 0.f, s2 = 0.f, s3 = 0.f, s4 = 0.f, s5 = 0.f, s6 = 0.f, s7 = 0.f;
    for (int tile = 0; tile < nt; ++tile) {
        const float4* p = (const float4*)(base + (size_t)tile * (T_ * 8));
        float4 v0 = p[0], v1 = p[1];
        s0 += v0.x; s1 += v0.y; s2 += v0.z; s3 += v0.w;
        s4 += v1.x; s5 += v1.y; s6 += v1.z; s7 += v1.w;
    }
    float sum = ((s0 + s1) + (s2 + s3)) + ((s4 + s5) + (s6 + s7));
    float m = sum / g_dsum;

    float hsc = 10.f * sigmoidf_(hr[0]);
    float msc = 10.f * sigmoidf_(mr[0]);
    float mof = fmaf(20.f, sigmoidf_(offr[0]), -10.f);

    float hv = dec[idx];
    out_b[idx] = fmaf(hsc, hv, fmaf(msc, m, mof));
    out_m[idx] = m;
}

// ---------------- host launcher -------------------------------------------
extern "C" void kernel_launch(void* const* d_in, const int* in_sizes, int n_in,
                              void* d_out, int out_size)
{
    const float* enc_in = (const float*)d_in[0];
    const float* dec    = (const float*)d_in[1];
    const float* maskp  = (const float*)d_in[2];
    const float* mesh   = (const float*)d_in[3];
    const float* dWin   = (const float*)d_in[4];
    const float* dbin   = (const float*)d_in[5];
    const float* dWr    = (const float*)d_in[6];
    const float* dbr    = (const float*)d_in[7];
    const float* dWout  = (const float*)d_in[8];
    const float* dbout  = (const float*)d_in[9];
    const float* eWs    = (const float*)d_in[10];
    const float* ebs    = (const float*)d_in[11];
    const float* eWm    = (const float*)d_in[12];
    const float* eWc    = (const float*)d_in[13];
    const float* ebm    = (const float*)d_in[14];
    const float* eWo    = (const float*)d_in[15];
    const float* ebo    = (const float*)d_in[16];
    const float* hr     = (const float*)d_in[17];
    const float* mr     = (const float*)d_in[18];
    const float* offr   = (const float*)d_in[19];

    const int M = in_sizes[3] / 2;   // 5151

    // n: grid points per axis with n*(n+1)/2 == M
    int n = 2;
    while (n * (n + 1) / 2 < M) ++n;   // -> 101

    // tile list (8 beta-steps x 12 alpha-steps per tile)
    Tiles tl;
    tl.n = n;
    tl.nt = 0;
    int ntb = (n + 7) / 8, nta = (n + 11) / 12;
    for (int tb = 0; tb < ntb; ++tb)
        for (int ta = 0; ta < nta; ++ta) {
            int ibmin = tb * 8;
            int iamax = ta * 12 + 11; if (iamax > n - 1) iamax = n - 1;
            if (iamax < ibmin) continue;            // no ia >= ib cells
            if (tl.nt < 120) { tl.tb[tl.nt] = (short)tb; tl.ta[tl.nt] = (short)ta; tl.nt++; }
        }
    if (tl.nt > NSLOT) tl.nt = NSLOT;              // safety (never hit for M=5151)
    int groups = (tl.nt + 7) / 8;                  // 9 for n=101

    // output layout: concat of (b_out, density, m, initial_states, mesh)
    float* out      = (float*)d_out;
    float* out_b    = out;
    float* out_dens = out_b    + B_ * T_;
    float* out_m    = out_dens + B_ * M;
    float* out_init = out_m    + B_ * T_;
    float* out_mesh = out_init + B_ * M;

    k_density<<<(M + 15) / 16, 128>>>(mesh, dWin, dbin, dWr, dbr, dWout, dbout, M);
    k_dsum<<<1, 256>>>(M);
    k_ctx<<<B_, 256>>>(enc_in, maskp, eWs, ebs, eWc, ebm);
    k_init<<<dim3((M + 127) / 128, B_), 128>>>(mesh, eWm, eWo, ebo, out_init, out_dens, out_mesh, M);
    k_scan<<<dim3(groups, B_), 256>>>(mesh, dec, M, tl);
    k_final<<<(B_ * T_) / 256, 256>>>(dec, hr, mr, offr, out_b, out_m, tl.nt);

    (void)n_in; (void)out_size;
}